// round 15
// baseline (speedup 1.0000x reference)
#include <cuda_runtime.h>
#include <cuda_bf16.h>
#include <cuda_fp16.h>
#include <cstdint>
#include <cstddef>

// Problem dims (fixed)
#define B_   2
#define NP_  512
#define NC_  512
#define D_   128
#define P_   128
#define NTILES 4096                       // B_*NP_*4 j-tiles

// ---------------- device scratch (allocation-free) ----------------
__device__ __align__(16) float    g_pn[(size_t)B_ * NP_ * D_];      // ln p, fp32
// c in mma-A-fragment layout: [blkm(64)][k16(8)][lane(32)][reg(4)] u32
__device__ __align__(16) uint32_t g_cfrag[(size_t)B_ * NC_ * D_ / 2];

__device__ __forceinline__ uint32_t smem_u32(const void* p) {
    uint32_t a;
    asm("{ .reg .u64 t; cvta.to.shared.u64 t, %1; cvt.u32.u64 %0, t; }"
        : "=r"(a) : "l"(p));
    return a;
}
__device__ __forceinline__ float4 shflx4(float4 v, int m) {
    double lo = __hiloint2double(__float_as_int(v.y), __float_as_int(v.x));
    double hi = __hiloint2double(__float_as_int(v.w), __float_as_int(v.z));
    lo = __shfl_xor_sync(0xFFFFFFFFu, lo, m);
    hi = __shfl_xor_sync(0xFFFFFFFFu, hi, m);
    return make_float4(__int_as_float(__double2loint(lo)),
                       __int_as_float(__double2hiint(lo)),
                       __int_as_float(__double2loint(hi)),
                       __int_as_float(__double2hiint(hi)));
}

// ---------------- SMEM layout ----------------
#define LDA      272                      // 128 fp16 = 256B + 16B pad
#define SM_P     0                        // 512 B
#define SM_BIAS  512                      // 512 B
#define SM_SCALE 1024                     // 2048 B
#define SM_B     3072
#define SM_TOTAL (SM_B + 128 * LDA)       // 37888 bytes

// ---------------------------------------------------------------------------
// LayerNorm: one warp per row. p rows -> fp32; c rows -> fragment-layout fp16.
// ---------------------------------------------------------------------------
__global__ void ln_kernel(const float* __restrict__ p_in,
                          const float* __restrict__ c_in,
                          const float* __restrict__ pw, const float* __restrict__ pb,
                          const float* __restrict__ cw, const float* __restrict__ cb) {
    int gwarp = (blockIdx.x * blockDim.x + threadIdx.x) >> 5;
    int lane  = threadIdx.x & 31;
    if (gwarp >= B_ * (NP_ + NC_)) return;

    bool is_p = gwarp < B_ * NP_;
    int row = is_p ? gwarp : gwarp - B_ * NP_;
    const float* src = is_p ? p_in : c_in;
    const float* w   = is_p ? pw : cw;
    const float* bb  = is_p ? pb : cb;

    float4 v = reinterpret_cast<const float4*>(src + (size_t)row * D_)[lane];

    float s = v.x + v.y + v.z + v.w;
    #pragma unroll
    for (int o = 16; o > 0; o >>= 1) s += __shfl_xor_sync(0xFFFFFFFFu, s, o);
    float mu = s * (1.0f / D_);

    float dx = v.x - mu, dy = v.y - mu, dz = v.z - mu, dw = v.w - mu;
    float q = dx * dx + dy * dy + dz * dz + dw * dw;
    #pragma unroll
    for (int o = 16; o > 0; o >>= 1) q += __shfl_xor_sync(0xFFFFFFFFu, q, o);
    float inv = rsqrtf(q * (1.0f / D_) + 1e-5f);

    float4 wv = reinterpret_cast<const float4*>(w)[lane];
    float4 bv = reinterpret_cast<const float4*>(bb)[lane];
    float o0 = dx * inv * wv.x + bv.x;
    float o1 = dy * inv * wv.y + bv.y;
    float o2 = dz * inv * wv.z + bv.z;
    float o3 = dw * inv * wv.w + bv.w;

    if (is_p) {
        float4 o4 = {o0, o1, o2, o3};
        reinterpret_cast<float4*>(g_pn + (size_t)row * D_)[lane] = o4;
    } else {
        // scatter into mma A-fragment layout
        __half2 h01 = __floats2half2_rn(o0, o1);
        __half2 h23 = __floats2half2_rn(o2, o3);
        uint32_t wrd[2];
        wrd[0] = *reinterpret_cast<uint32_t*>(&h01);   // k = 4*lane, 4*lane+1
        wrd[1] = *reinterpret_cast<uint32_t*>(&h23);   // k = 4*lane+2, +3
        const int r = row & 15;
        const size_t blkm = (size_t)(row >> 4);
        const int k0 = lane * 4;
        #pragma unroll
        for (int m = 0; m < 2; m++) {
            int kg  = k0 + 2 * m;
            int k16 = kg >> 4;
            int kk  = kg & 15;
            int lp  = (r & 7) * 4 + ((kk >> 1) & 3);
            int rg  = (r >> 3) + 2 * (kk >> 3);
            g_cfrag[((blkm * 8 + k16) * 32 + lp) * 4 + rg] = wrd[m];
        }
    }
}

// ---------------------------------------------------------------------------
// PERSISTENT-WORKER fp16 warp-MMA interaction kernel, A direct from GMEM,
// epilogue with FULL-128B-LINE stores (xor-1 + xor-4 shuffle stages).
// Grid = nworkers (~3 x SMs). 128 threads = 4 warps in 2(m) x 2(n).
// mask_mode: 0=none, 1=float per entry, 2=byte per entry.
// ---------------------------------------------------------------------------
__global__ __launch_bounds__(128, 3)
void gemm_mma_kernel(const int* __restrict__ p_mask,
                     const int* __restrict__ c_mask,
                     const float* __restrict__ W,
                     const float* __restrict__ bias,
                     float* __restrict__ out,
                     void* __restrict__ mask_out, int mask_mode) {
    extern __shared__ char smem[];
    const uint32_t sb = smem_u32(smem);
    float* p_s     = reinterpret_cast<float*>(smem + SM_P);
    float* bias_s  = reinterpret_cast<float*>(smem + SM_BIAS);
    float* scale_s = reinterpret_cast<float*>(smem + SM_SCALE);

    const int t = threadIdx.x;
    const int wid  = t >> 5;
    const int lane = t & 31;
    const int nw = gridDim.x;
    const int w  = blockIdx.x;

    const int start = (int)(((long)w * NTILES) / nw);
    const int end   = (int)(((long)(w + 1) * NTILES) / nw);
    if (start >= end) return;

    // --- bias load (once) ---
    if (t < 32) {
        reinterpret_cast<float4*>(bias_s)[t] =
            reinterpret_cast<const float4*>(bias)[t];
    }

    const int wm = wid & 1;      // m: 64 j-rows each
    const int wn = wid >> 1;     // n: 64 h-cols each
    const uint32_t b_lane = (uint32_t)((wn * 64 + (lane & 15)) * LDA + (lane >> 4) * 16);
    const uint32_t bhbase = sb + SM_B + b_lane;

    const int g   = lane >> 2;
    const int tig = lane & 3;
    const int odd = tig & 1;
    const int colq = (tig >> 1) * 4;     // 0 or 4
    const int godd = g & 1;

    int prev_bi = -1;

    #pragma unroll 1
    for (int tidx = start; tidx < end; tidx++) {
        const int b  = tidx >> 11;
        const int bi = tidx >> 2;            // (b*512 + i)
        const int jt = tidx & 3;
        const int j0 = jt * 128;

        // --- rebuild per-i state on i change ---
        if (bi != prev_bi) {
            __syncthreads();     // all warps done with previous B/scale
            if (t < 32) {
                float4 v = reinterpret_cast<const float4*>(
                    g_pn + ((size_t)bi) * D_)[t];
                p_s[t * 4 + 0] = v.x; p_s[t * 4 + 1] = v.y;
                p_s[t * 4 + 2] = v.z; p_s[t * 4 + 3] = v.w;
            }
            {
                const bool pm = p_mask[bi] != 0;
                const int4 cm = reinterpret_cast<const int4*>(c_mask + b * NC_)[t];
                float4 sc;
                sc.x = (pm && cm.x) ? 1.0f : 0.0f;
                sc.y = (pm && cm.y) ? 1.0f : 0.0f;
                sc.z = (pm && cm.z) ? 1.0f : 0.0f;
                sc.w = (pm && cm.w) ? 1.0f : 0.0f;
                reinterpret_cast<float4*>(scale_s)[t] = sc;
            }
            __syncthreads();     // p_s + scale_s visible

            // fused inter_mask row write (only owner of jt==0 writes)
            if (jt == 0) {
                if (mask_mode == 1) {
                    float* mrow = reinterpret_cast<float*>(mask_out) + (size_t)bi * NC_;
                    reinterpret_cast<float4*>(mrow)[t] =
                        reinterpret_cast<float4*>(scale_s)[t];
                } else if (mask_mode == 2) {
                    unsigned char* mrow = reinterpret_cast<unsigned char*>(mask_out)
                                        + (size_t)bi * NC_;
                    float4 sc = reinterpret_cast<float4*>(scale_s)[t];
                    uchar4 u;
                    u.x = (unsigned char)(sc.x != 0.0f);
                    u.y = (unsigned char)(sc.y != 0.0f);
                    u.z = (unsigned char)(sc.z != 0.0f);
                    u.w = (unsigned char)(sc.w != 0.0f);
                    reinterpret_cast<uchar4*>(mrow)[t] = u;
                }
            }

            // build B = W o p_i, fp16
            #pragma unroll 4
            for (int u = t; u < 4096; u += 128) {
                int row = u >> 5;
                int q   = u & 31;
                float4 w4 = reinterpret_cast<const float4*>(W + (size_t)row * D_)[q];
                int k = q * 4;
                __half2 h01 = __floats2half2_rn(w4.x * p_s[k + 0], w4.y * p_s[k + 1]);
                __half2 h23 = __floats2half2_rn(w4.z * p_s[k + 2], w4.w * p_s[k + 3]);
                uint2 hw;
                hw.x = *reinterpret_cast<uint32_t*>(&h01);
                hw.y = *reinterpret_cast<uint32_t*>(&h23);
                *reinterpret_cast<uint2*>(smem + SM_B + row * LDA + k * 2) = hw;
            }
            __syncthreads();     // B visible to all warps
            prev_bi = bi;
        }

        // --- A fragment base for this tile (L2-hot, coalesced uint4 loads) ---
        const int bjrow = b * NC_ + j0 + wm * 64; // global c row base (mult of 16)
        const uint4* abase4 = reinterpret_cast<const uint4*>(g_cfrag)
                            + ((size_t)(bjrow >> 4)) * 256 + lane;

        // --- Mainloop: warp tile 64x64, A via LDG, B via LDSM ---
        float acc[4][8][4];
        #pragma unroll
        for (int mf = 0; mf < 4; mf++)
            #pragma unroll
            for (int nf = 0; nf < 8; nf++)
                #pragma unroll
                for (int r = 0; r < 4; r++) acc[mf][nf][r] = 0.0f;

        #pragma unroll
        for (int ks = 0; ks < 8; ks++) {
            uint32_t bh[4][4];
            #pragma unroll
            for (int np = 0; np < 4; np++) {
                uint32_t addr = bhbase + np * (16 * LDA) + ks * 32;
                asm volatile("ldmatrix.sync.aligned.m8n8.x4.shared.b16 {%0,%1,%2,%3}, [%4];"
                             : "=r"(bh[np][0]), "=r"(bh[np][1]),
                               "=r"(bh[np][2]), "=r"(bh[np][3]) : "r"(addr));
            }
            #pragma unroll
            for (int mf = 0; mf < 4; mf++) {
                const uint4 av = __ldg(abase4 + mf * 256 + ks * 32);
                #pragma unroll
                for (int np = 0; np < 4; np++) {
                    #pragma unroll
                    for (int sel = 0; sel < 2; sel++) {
                        const int nf = np * 2 + sel;
                        asm volatile(
                            "mma.sync.aligned.m16n8k16.row.col.f32.f16.f16.f32 "
                            "{%0,%1,%2,%3}, {%4,%5,%6,%7}, {%8,%9}, {%0,%1,%2,%3};"
                            : "+f"(acc[mf][nf][0]), "+f"(acc[mf][nf][1]),
                              "+f"(acc[mf][nf][2]), "+f"(acc[mf][nf][3])
                            : "r"(av.x), "r"(av.y), "r"(av.z), "r"(av.w),
                              "r"(bh[np][sel]), "r"(bh[np][2 + sel]));
                    }
                }
            }
        }

        // --- Epilogue: bias + mask; xor-1 + xor-4 stages -> full-line stores ---
        float s0a[4], s1a[4];
        #pragma unroll
        for (int mf = 0; mf < 4; mf++) {
            const int jlg = j0 + wm * 64 + mf * 16 + g;
            s0a[mf] = scale_s[jlg];
            s1a[mf] = scale_s[jlg + 8];
        }
        float* basep = out + ((size_t)bi * NC_ + j0 + wm * 64) * P_;

        #pragma unroll
        for (int Ph = 0; Ph < 2; Ph++) {
            const int nfA0 = 4 * Ph, nfA1 = nfA0 + 1, nfB0 = nfA0 + 2, nfB1 = nfA0 + 3;
            const float2 bA0 = *reinterpret_cast<const float2*>(bias_s + wn * 64 + nfA0 * 8 + tig * 2);
            const float2 bA1 = *reinterpret_cast<const float2*>(bias_s + wn * 64 + nfA1 * 8 + tig * 2);
            const float2 bB0 = *reinterpret_cast<const float2*>(bias_s + wn * 64 + nfB0 * 8 + tig * 2);
            const float2 bB1 = *reinterpret_cast<const float2*>(bias_s + wn * 64 + nfB1 * 8 + tig * 2);
            const int colA = wn * 64 + (odd ? nfA1 : nfA0) * 8 + colq;
            const int colB = wn * 64 + (odd ? nfB1 : nfB0) * 8 + colq;
            const int colE = godd ? colB : colA;
            const int colO = godd ? colA : colB;

            #pragma unroll
            for (int mf = 0; mf < 4; mf++) {
                const float s0 = s0a[mf], s1 = s1a[mf];

                // ---- build pair-A float4s (xor-1 stage) ----
                float a0 = (acc[mf][nfA0][0] + bA0.x) * s0;
                float a1 = (acc[mf][nfA0][1] + bA0.y) * s0;
                float v0 = (acc[mf][nfA1][0] + bA1.x) * s0;
                float v1 = (acc[mf][nfA1][1] + bA1.y) * s0;
                float c0 = (acc[mf][nfA0][2] + bA0.x) * s1;
                float c1 = (acc[mf][nfA0][3] + bA0.y) * s1;
                float d0 = (acc[mf][nfA1][2] + bA1.x) * s1;
                float d1 = (acc[mf][nfA1][3] + bA1.y) * s1;
                double pa = __hiloint2double(__float_as_int(a1), __float_as_int(a0));
                double pb = __hiloint2double(__float_as_int(v1), __float_as_int(v0));
                double pc = __hiloint2double(__float_as_int(c1), __float_as_int(c0));
                double pd = __hiloint2double(__float_as_int(d1), __float_as_int(d0));
                double ra = __shfl_xor_sync(0xFFFFFFFFu, pa, 1);
                double rb = __shfl_xor_sync(0xFFFFFFFFu, pb, 1);
                double rc = __shfl_xor_sync(0xFFFFFFFFu, pc, 1);
                double rd = __shfl_xor_sync(0xFFFFFFFFu, pd, 1);
                float4 f4a_r0, f4a_r1;
                if (!odd) {
                    f4a_r0 = make_float4(a0, a1, __int_as_float(__double2loint(ra)),
                                                  __int_as_float(__double2hiint(ra)));
                    f4a_r1 = make_float4(c0, c1, __int_as_float(__double2loint(rc)),
                                                  __int_as_float(__double2hiint(rc)));
                } else {
                    f4a_r0 = make_float4(__int_as_float(__double2loint(rb)),
                                         __int_as_float(__double2hiint(rb)), v0, v1);
                    f4a_r1 = make_float4(__int_as_float(__double2loint(rd)),
                                         __int_as_float(__double2hiint(rd)), d0, d1);
                }

                // ---- build pair-B float4s (xor-1 stage) ----
                a0 = (acc[mf][nfB0][0] + bB0.x) * s0;
                a1 = (acc[mf][nfB0][1] + bB0.y) * s0;
                v0 = (acc[mf][nfB1][0] + bB1.x) * s0;
                v1 = (acc[mf][nfB1][1] + bB1.y) * s0;
                c0 = (acc[mf][nfB0][2] + bB0.x) * s1;
                c1 = (acc[mf][nfB0][3] + bB0.y) * s1;
                d0 = (acc[mf][nfB1][2] + bB1.x) * s1;
                d1 = (acc[mf][nfB1][3] + bB1.y) * s1;
                pa = __hiloint2double(__float_as_int(a1), __float_as_int(a0));
                pb = __hiloint2double(__float_as_int(v1), __float_as_int(v0));
                pc = __hiloint2double(__float_as_int(c1), __float_as_int(c0));
                pd = __hiloint2double(__float_as_int(d1), __float_as_int(d0));
                ra = __shfl_xor_sync(0xFFFFFFFFu, pa, 1);
                rb = __shfl_xor_sync(0xFFFFFFFFu, pb, 1);
                rc = __shfl_xor_sync(0xFFFFFFFFu, pc, 1);
                rd = __shfl_xor_sync(0xFFFFFFFFu, pd, 1);
                float4 f4b_r0, f4b_r1;
                if (!odd) {
                    f4b_r0 = make_float4(a0, a1, __int_as_float(__double2loint(ra)),
                                                  __int_as_float(__double2hiint(ra)));
                    f4b_r1 = make_float4(c0, c1, __int_as_float(__double2loint(rc)),
                                                  __int_as_float(__double2hiint(rc)));
                } else {
                    f4b_r0 = make_float4(__int_as_float(__double2loint(rb)),
                                         __int_as_float(__double2hiint(rb)), v0, v1);
                    f4b_r1 = make_float4(__int_as_float(__double2loint(rd)),
                                         __int_as_float(__double2hiint(rd)), d0, d1);
                }

                // ---- xor-4 swap of pair-B data (row g <-> g^1) ----
                float4 f4bs_r0 = shflx4(f4b_r0, 4);
                float4 f4bs_r1 = shflx4(f4b_r1, 4);

                // ---- full-line stores: E = even rows, O = odd rows ----
                float* mfp = basep + (size_t)(mf * 16) * P_;
                float* rE = mfp + (size_t)(g & ~1) * P_;
                float* rO = mfp + (size_t)(g | 1) * P_;
                float4 vE0 = godd ? f4bs_r0 : f4a_r0;
                float4 vO0 = godd ? f4a_r0 : f4bs_r0;
                float4 vE1 = godd ? f4bs_r1 : f4a_r1;
                float4 vO1 = godd ? f4a_r1 : f4bs_r1;
                asm volatile("st.global.cs.v4.f32 [%0], {%1, %2, %3, %4};"
                             :: "l"(rE + colE), "f"(vE0.x), "f"(vE0.y), "f"(vE0.z), "f"(vE0.w)
                             : "memory");
                asm volatile("st.global.cs.v4.f32 [%0], {%1, %2, %3, %4};"
                             :: "l"(rO + colO), "f"(vO0.x), "f"(vO0.y), "f"(vO0.z), "f"(vO0.w)
                             : "memory");
                asm volatile("st.global.cs.v4.f32 [%0], {%1, %2, %3, %4};"
                             :: "l"(rE + 8 * P_ + colE), "f"(vE1.x), "f"(vE1.y), "f"(vE1.z), "f"(vE1.w)
                             : "memory");
                asm volatile("st.global.cs.v4.f32 [%0], {%1, %2, %3, %4};"
                             :: "l"(rO + 8 * P_ + colO), "f"(vO1.x), "f"(vO1.y), "f"(vO1.z), "f"(vO1.w)
                             : "memory");
            }
        }
    }
}

// ---------------------------------------------------------------------------
// Fallback inter_mask kernel (only for unexpected tail sizes)
// ---------------------------------------------------------------------------
__global__ void mask_float_kernel(const int* __restrict__ p_mask,
                                  const int* __restrict__ c_mask,
                                  float* __restrict__ out, long n) {
    long idx = (long)blockIdx.x * blockDim.x + threadIdx.x;
    if (idx >= n) return;
    int j  = (int)(idx & (NC_ - 1));
    long bi = idx >> 9;
    int i  = (int)(bi & (NP_ - 1));
    int b  = (int)(bi >> 9);
    out[idx] = (p_mask[b * NP_ + i] && c_mask[b * NC_ + j]) ? 1.0f : 0.0f;
}

// ---------------------------------------------------------------------------
extern "C" void kernel_launch(void* const* d_in, const int* in_sizes, int n_in,
                              void* d_out, int out_size) {
    const float* p_embed = (const float*)d_in[0];
    const float* c_embed = (const float*)d_in[1];
    const int*   p_mask  = (const int*)d_in[2];
    const int*   c_mask  = (const int*)d_in[3];
    const float* ln_p_w  = (const float*)d_in[4];
    const float* ln_p_b  = (const float*)d_in[5];
    const float* ln_c_w  = (const float*)d_in[6];
    const float* ln_c_b  = (const float*)d_in[7];
    const float* W_out   = (const float*)d_in[8];
    const float* b_out   = (const float*)d_in[9];
    float* out = (float*)d_out;

    cudaFuncSetAttribute(gemm_mma_kernel,
                         cudaFuncAttributeMaxDynamicSharedMemorySize, SM_TOTAL);

    // LayerNorm (p -> fp32, c -> fragment-layout fp16)
    ln_kernel<<<(B_ * (NP_ + NC_)) / 8, 256>>>(p_embed, c_embed,
                                               ln_p_w, ln_p_b, ln_c_w, ln_c_b);

    // Decide inter_mask tail format
    const long inter_elems = (long)B_ * NP_ * NC_ * P_;
    const long mask_elems  = (long)B_ * NP_ * NC_;
    long extra = (long)out_size - inter_elems;
    void* mask_out = nullptr;
    int mask_mode = 0;
    if (extra >= mask_elems) {
        mask_out = (void*)(out + inter_elems); mask_mode = 1;      // float per entry
    } else if (extra == mask_elems / 4) {
        mask_out = (void*)(out + inter_elems); mask_mode = 2;      // byte per entry
    }

    // Persistent workers: 3 per SM
    int sms = 148;
    cudaDeviceGetAttribute(&sms, cudaDevAttrMultiProcessorCount, 0);
    int nworkers = sms * 3;
    if (nworkers > NTILES) nworkers = NTILES;

    gemm_mma_kernel<<<nworkers, 128, SM_TOTAL>>>(p_mask, c_mask, W_out, b_out, out,
                                                 mask_out, mask_mode);

    // Fallback for odd partial tails only
    if (mask_mode == 0 && extra > 0) {
        long n = extra < mask_elems ? extra : mask_elems;
        mask_float_kernel<<<(int)((n + 255) / 256), 256>>>(
            p_mask, c_mask, out + inter_elems, n);
    }
}

// round 16
// speedup vs baseline: 1.4659x; 1.4659x over previous
#include <cuda_runtime.h>
#include <cuda_bf16.h>
#include <cuda_fp16.h>
#include <cstdint>
#include <cstddef>

// Problem dims (fixed)
#define B_   2
#define NP_  512
#define NC_  512
#define D_   128
#define P_   128
#define NTILES 4096                       // B_*NP_*4 j-tiles

// ---------------- device scratch (allocation-free) ----------------
__device__ __align__(16) float    g_pn[(size_t)B_ * NP_ * D_];      // ln p, fp32
// c in mma-A-fragment layout: [blkm(64)][k16(8)][lane(32)][reg(4)] u32
__device__ __align__(16) uint32_t g_cfrag[(size_t)B_ * NC_ * D_ / 2];

__device__ __forceinline__ uint32_t smem_u32(const void* p) {
    uint32_t a;
    asm("{ .reg .u64 t; cvta.to.shared.u64 t, %1; cvt.u32.u64 %0, t; }"
        : "=r"(a) : "l"(p));
    return a;
}

// ---------------- SMEM layout ----------------
#define LDA      272                      // 128 fp16 = 256B + 16B pad
#define SM_P     0                        // 512 B
#define SM_BIAS  512                      // 512 B
#define SM_SCALE 1024                     // 2048 B
#define SM_B     3072
#define SM_TOTAL (SM_B + 128 * LDA)       // 37888 bytes

// ---------------------------------------------------------------------------
// LayerNorm: one warp per row. p rows -> fp32; c rows -> fragment-layout fp16.
// ---------------------------------------------------------------------------
__global__ void ln_kernel(const float* __restrict__ p_in,
                          const float* __restrict__ c_in,
                          const float* __restrict__ pw, const float* __restrict__ pb,
                          const float* __restrict__ cw, const float* __restrict__ cb) {
    int gwarp = (blockIdx.x * blockDim.x + threadIdx.x) >> 5;
    int lane  = threadIdx.x & 31;
    if (gwarp >= B_ * (NP_ + NC_)) return;

    bool is_p = gwarp < B_ * NP_;
    int row = is_p ? gwarp : gwarp - B_ * NP_;
    const float* src = is_p ? p_in : c_in;
    const float* w   = is_p ? pw : cw;
    const float* bb  = is_p ? pb : cb;

    float4 v = reinterpret_cast<const float4*>(src + (size_t)row * D_)[lane];

    float s = v.x + v.y + v.z + v.w;
    #pragma unroll
    for (int o = 16; o > 0; o >>= 1) s += __shfl_xor_sync(0xFFFFFFFFu, s, o);
    float mu = s * (1.0f / D_);

    float dx = v.x - mu, dy = v.y - mu, dz = v.z - mu, dw = v.w - mu;
    float q = dx * dx + dy * dy + dz * dz + dw * dw;
    #pragma unroll
    for (int o = 16; o > 0; o >>= 1) q += __shfl_xor_sync(0xFFFFFFFFu, q, o);
    float inv = rsqrtf(q * (1.0f / D_) + 1e-5f);

    float4 wv = reinterpret_cast<const float4*>(w)[lane];
    float4 bv = reinterpret_cast<const float4*>(bb)[lane];
    float o0 = dx * inv * wv.x + bv.x;
    float o1 = dy * inv * wv.y + bv.y;
    float o2 = dz * inv * wv.z + bv.z;
    float o3 = dw * inv * wv.w + bv.w;

    if (is_p) {
        float4 o4 = {o0, o1, o2, o3};
        reinterpret_cast<float4*>(g_pn + (size_t)row * D_)[lane] = o4;
    } else {
        // scatter into mma A-fragment layout
        __half2 h01 = __floats2half2_rn(o0, o1);
        __half2 h23 = __floats2half2_rn(o2, o3);
        uint32_t wrd[2];
        wrd[0] = *reinterpret_cast<uint32_t*>(&h01);   // k = 4*lane, 4*lane+1
        wrd[1] = *reinterpret_cast<uint32_t*>(&h23);   // k = 4*lane+2, +3
        const int r = row & 15;
        const size_t blkm = (size_t)(row >> 4);
        const int k0 = lane * 4;
        #pragma unroll
        for (int m = 0; m < 2; m++) {
            int kg  = k0 + 2 * m;
            int k16 = kg >> 4;
            int kk  = kg & 15;
            int lp  = (r & 7) * 4 + ((kk >> 1) & 3);
            int rg  = (r >> 3) + 2 * (kk >> 3);
            g_cfrag[((blkm * 8 + k16) * 32 + lp) * 4 + rg] = wrd[m];
        }
    }
}

// ---------------------------------------------------------------------------
// PERSISTENT-WORKER fp16 warp-MMA interaction kernel, A direct from GMEM with
// batched MLP=4 loads per ks. Grid = nworkers (~3 x SMs). 128 threads =
// 4 warps in 2(m) x 2(n), warp tile 64x64.
// mask_mode: 0=none, 1=float per entry, 2=byte per entry.
// ---------------------------------------------------------------------------
__global__ __launch_bounds__(128, 3)
void gemm_mma_kernel(const int* __restrict__ p_mask,
                     const int* __restrict__ c_mask,
                     const float* __restrict__ W,
                     const float* __restrict__ bias,
                     float* __restrict__ out,
                     void* __restrict__ mask_out, int mask_mode) {
    extern __shared__ char smem[];
    const uint32_t sb = smem_u32(smem);
    float* p_s     = reinterpret_cast<float*>(smem + SM_P);
    float* bias_s  = reinterpret_cast<float*>(smem + SM_BIAS);
    float* scale_s = reinterpret_cast<float*>(smem + SM_SCALE);

    const int t = threadIdx.x;
    const int wid  = t >> 5;
    const int lane = t & 31;
    const int nw = gridDim.x;
    const int w  = blockIdx.x;

    const int start = (int)(((long)w * NTILES) / nw);
    const int end   = (int)(((long)(w + 1) * NTILES) / nw);
    if (start >= end) return;

    // --- bias load (once) ---
    if (t < 32) {
        reinterpret_cast<float4*>(bias_s)[t] =
            reinterpret_cast<const float4*>(bias)[t];
    }

    const int wm = wid & 1;      // m: 64 j-rows each
    const int wn = wid >> 1;     // n: 64 h-cols each
    const uint32_t b_lane = (uint32_t)((wn * 64 + (lane & 15)) * LDA + (lane >> 4) * 16);
    const uint32_t bhbase = sb + SM_B + b_lane;

    const int g   = lane >> 2;
    const int tig = lane & 3;
    const int odd = tig & 1;
    const int colq = (tig >> 1) * 4;     // 0 or 4

    int prev_bi = -1;

    #pragma unroll 1
    for (int tidx = start; tidx < end; tidx++) {
        const int b  = tidx >> 11;
        const int bi = tidx >> 2;            // (b*512 + i)
        const int jt = tidx & 3;
        const int j0 = jt * 128;

        // --- rebuild per-i state on i change ---
        if (bi != prev_bi) {
            __syncthreads();     // all warps done with previous B/scale
            if (t < 32) {
                float4 v = reinterpret_cast<const float4*>(
                    g_pn + ((size_t)bi) * D_)[t];
                p_s[t * 4 + 0] = v.x; p_s[t * 4 + 1] = v.y;
                p_s[t * 4 + 2] = v.z; p_s[t * 4 + 3] = v.w;
            }
            {
                const bool pm = p_mask[bi] != 0;
                const int4 cm = reinterpret_cast<const int4*>(c_mask + b * NC_)[t];
                float4 sc;
                sc.x = (pm && cm.x) ? 1.0f : 0.0f;
                sc.y = (pm && cm.y) ? 1.0f : 0.0f;
                sc.z = (pm && cm.z) ? 1.0f : 0.0f;
                sc.w = (pm && cm.w) ? 1.0f : 0.0f;
                reinterpret_cast<float4*>(scale_s)[t] = sc;
            }
            __syncthreads();     // p_s + scale_s visible

            // fused inter_mask row write (only owner of jt==0 writes)
            if (jt == 0) {
                if (mask_mode == 1) {
                    float* mrow = reinterpret_cast<float*>(mask_out) + (size_t)bi * NC_;
                    reinterpret_cast<float4*>(mrow)[t] =
                        reinterpret_cast<float4*>(scale_s)[t];
                } else if (mask_mode == 2) {
                    unsigned char* mrow = reinterpret_cast<unsigned char*>(mask_out)
                                        + (size_t)bi * NC_;
                    float4 sc = reinterpret_cast<float4*>(scale_s)[t];
                    uchar4 u;
                    u.x = (unsigned char)(sc.x != 0.0f);
                    u.y = (unsigned char)(sc.y != 0.0f);
                    u.z = (unsigned char)(sc.z != 0.0f);
                    u.w = (unsigned char)(sc.w != 0.0f);
                    reinterpret_cast<uchar4*>(mrow)[t] = u;
                }
            }

            // build B = W o p_i, fp16
            #pragma unroll 4
            for (int u = t; u < 4096; u += 128) {
                int row = u >> 5;
                int q   = u & 31;
                float4 w4 = reinterpret_cast<const float4*>(W + (size_t)row * D_)[q];
                int k = q * 4;
                __half2 h01 = __floats2half2_rn(w4.x * p_s[k + 0], w4.y * p_s[k + 1]);
                __half2 h23 = __floats2half2_rn(w4.z * p_s[k + 2], w4.w * p_s[k + 3]);
                uint2 hw;
                hw.x = *reinterpret_cast<uint32_t*>(&h01);
                hw.y = *reinterpret_cast<uint32_t*>(&h23);
                *reinterpret_cast<uint2*>(smem + SM_B + row * LDA + k * 2) = hw;
            }
            __syncthreads();     // B visible to all warps
            prev_bi = bi;
        }

        // --- A fragment base for this tile (L2-hot, coalesced uint4 loads) ---
        const int bjrow = b * NC_ + j0 + wm * 64; // global c row base (mult of 16)
        const uint4* abase4 = reinterpret_cast<const uint4*>(g_cfrag)
                            + ((size_t)(bjrow >> 4)) * 256 + lane;

        // --- Mainloop: warp tile 64x64; A batched LDG (MLP=4), B LDSM halves ---
        float acc[4][8][4];
        #pragma unroll
        for (int mf = 0; mf < 4; mf++)
            #pragma unroll
            for (int nf = 0; nf < 8; nf++)
                #pragma unroll
                for (int r = 0; r < 4; r++) acc[mf][nf][r] = 0.0f;

        #pragma unroll
        for (int ks = 0; ks < 8; ks++) {
            // Batch all 4 A loads first (longest latency, MLP=4)
            uint4 av[4];
            #pragma unroll
            for (int mf = 0; mf < 4; mf++)
                av[mf] = __ldg(abase4 + mf * 256 + ks * 32);

            // B half 1 (np = 0,1)
            uint32_t bh[2][4];
            #pragma unroll
            for (int np = 0; np < 2; np++) {
                uint32_t addr = bhbase + np * (16 * LDA) + ks * 32;
                asm volatile("ldmatrix.sync.aligned.m8n8.x4.shared.b16 {%0,%1,%2,%3}, [%4];"
                             : "=r"(bh[np][0]), "=r"(bh[np][1]),
                               "=r"(bh[np][2]), "=r"(bh[np][3]) : "r"(addr));
            }
            #pragma unroll
            for (int mf = 0; mf < 4; mf++) {
                #pragma unroll
                for (int np = 0; np < 2; np++) {
                    #pragma unroll
                    for (int sel = 0; sel < 2; sel++) {
                        const int nf = np * 2 + sel;
                        asm volatile(
                            "mma.sync.aligned.m16n8k16.row.col.f32.f16.f16.f32 "
                            "{%0,%1,%2,%3}, {%4,%5,%6,%7}, {%8,%9}, {%0,%1,%2,%3};"
                            : "+f"(acc[mf][nf][0]), "+f"(acc[mf][nf][1]),
                              "+f"(acc[mf][nf][2]), "+f"(acc[mf][nf][3])
                            : "r"(av[mf].x), "r"(av[mf].y), "r"(av[mf].z), "r"(av[mf].w),
                              "r"(bh[np][sel]), "r"(bh[np][2 + sel]));
                    }
                }
            }

            // B half 2 (np = 2,3) reusing bh registers
            #pragma unroll
            for (int np = 0; np < 2; np++) {
                uint32_t addr = bhbase + (np + 2) * (16 * LDA) + ks * 32;
                asm volatile("ldmatrix.sync.aligned.m8n8.x4.shared.b16 {%0,%1,%2,%3}, [%4];"
                             : "=r"(bh[np][0]), "=r"(bh[np][1]),
                               "=r"(bh[np][2]), "=r"(bh[np][3]) : "r"(addr));
            }
            #pragma unroll
            for (int mf = 0; mf < 4; mf++) {
                #pragma unroll
                for (int np = 0; np < 2; np++) {
                    #pragma unroll
                    for (int sel = 0; sel < 2; sel++) {
                        const int nf = (np + 2) * 2 + sel;
                        asm volatile(
                            "mma.sync.aligned.m16n8k16.row.col.f32.f16.f16.f32 "
                            "{%0,%1,%2,%3}, {%4,%5,%6,%7}, {%8,%9}, {%0,%1,%2,%3};"
                            : "+f"(acc[mf][nf][0]), "+f"(acc[mf][nf][1]),
                              "+f"(acc[mf][nf][2]), "+f"(acc[mf][nf][3])
                            : "r"(av[mf].x), "r"(av[mf].y), "r"(av[mf].z), "r"(av[mf].w),
                              "r"(bh[np][sel]), "r"(bh[np][2 + sel]));
                    }
                }
            }
        }

        // --- Epilogue: bias + mask, float4 stores via pairwise exchange ---
        #pragma unroll
        for (int mf = 0; mf < 4; mf++) {
            const int jl = j0 + wm * 64 + mf * 16 + g;
            const float s0 = scale_s[jl];
            const float s1 = scale_s[jl + 8];
            float* rowp  = out + ((size_t)bi * NC_ + jl) * P_ + wn * 64;
            float* row1p = rowp + (size_t)8 * P_;
            #pragma unroll
            for (int nfp = 0; nfp < 4; nfp++) {
                const int nf0 = nfp * 2, nf1 = nf0 + 1;
                const int h0 = wn * 64 + nf0 * 8 + tig * 2;
                const int h1 = wn * 64 + nf1 * 8 + tig * 2;
                float a0 = (acc[mf][nf0][0] + bias_s[h0])     * s0;
                float a1 = (acc[mf][nf0][1] + bias_s[h0 + 1]) * s0;
                float bv0 = (acc[mf][nf1][0] + bias_s[h1])     * s0;
                float bv1 = (acc[mf][nf1][1] + bias_s[h1 + 1]) * s0;
                float c0 = (acc[mf][nf0][2] + bias_s[h0])     * s1;
                float c1 = (acc[mf][nf0][3] + bias_s[h0 + 1]) * s1;
                float d0 = (acc[mf][nf1][2] + bias_s[h1])     * s1;
                float d1 = (acc[mf][nf1][3] + bias_s[h1 + 1]) * s1;

                double pa = __hiloint2double(__float_as_int(a1), __float_as_int(a0));
                double pb = __hiloint2double(__float_as_int(bv1), __float_as_int(bv0));
                double pc = __hiloint2double(__float_as_int(c1), __float_as_int(c0));
                double pd = __hiloint2double(__float_as_int(d1), __float_as_int(d0));
                double ra = __shfl_xor_sync(0xFFFFFFFFu, pa, 1);
                double rb = __shfl_xor_sync(0xFFFFFFFFu, pb, 1);
                double rc = __shfl_xor_sync(0xFFFFFFFFu, pc, 1);
                double rd = __shfl_xor_sync(0xFFFFFFFFu, pd, 1);
                float rax = __int_as_float(__double2loint(ra)), ray = __int_as_float(__double2hiint(ra));
                float rbx = __int_as_float(__double2loint(rb)), rby = __int_as_float(__double2hiint(rb));
                float rcx = __int_as_float(__double2loint(rc)), rcy = __int_as_float(__double2hiint(rc));
                float rdx = __int_as_float(__double2loint(rd)), rdy = __int_as_float(__double2hiint(rd));

                const int col = (odd ? nf1 : nf0) * 8 + colq;
                float4 v0, v1;
                if (!odd) {
                    v0 = make_float4(a0, a1, rax, ray);
                    v1 = make_float4(c0, c1, rcx, rcy);
                } else {
                    v0 = make_float4(rbx, rby, bv0, bv1);
                    v1 = make_float4(rdx, rdy, d0, d1);
                }
                asm volatile("st.global.cs.v4.f32 [%0], {%1, %2, %3, %4};"
                             :: "l"(rowp + col), "f"(v0.x), "f"(v0.y), "f"(v0.z), "f"(v0.w)
                             : "memory");
                asm volatile("st.global.cs.v4.f32 [%0], {%1, %2, %3, %4};"
                             :: "l"(row1p + col), "f"(v1.x), "f"(v1.y), "f"(v1.z), "f"(v1.w)
                             : "memory");
            }
        }
    }
}

// ---------------------------------------------------------------------------
// Fallback inter_mask kernel (only for unexpected tail sizes)
// ---------------------------------------------------------------------------
__global__ void mask_float_kernel(const int* __restrict__ p_mask,
                                  const int* __restrict__ c_mask,
                                  float* __restrict__ out, long n) {
    long idx = (long)blockIdx.x * blockDim.x + threadIdx.x;
    if (idx >= n) return;
    int j  = (int)(idx & (NC_ - 1));
    long bi = idx >> 9;
    int i  = (int)(bi & (NP_ - 1));
    int b  = (int)(bi >> 9);
    out[idx] = (p_mask[b * NP_ + i] && c_mask[b * NC_ + j]) ? 1.0f : 0.0f;
}

// ---------------------------------------------------------------------------
extern "C" void kernel_launch(void* const* d_in, const int* in_sizes, int n_in,
                              void* d_out, int out_size) {
    const float* p_embed = (const float*)d_in[0];
    const float* c_embed = (const float*)d_in[1];
    const int*   p_mask  = (const int*)d_in[2];
    const int*   c_mask  = (const int*)d_in[3];
    const float* ln_p_w  = (const float*)d_in[4];
    const float* ln_p_b  = (const float*)d_in[5];
    const float* ln_c_w  = (const float*)d_in[6];
    const float* ln_c_b  = (const float*)d_in[7];
    const float* W_out   = (const float*)d_in[8];
    const float* b_out   = (const float*)d_in[9];
    float* out = (float*)d_out;

    cudaFuncSetAttribute(gemm_mma_kernel,
                         cudaFuncAttributeMaxDynamicSharedMemorySize, SM_TOTAL);

    // LayerNorm (p -> fp32, c -> fragment-layout fp16)
    ln_kernel<<<(B_ * (NP_ + NC_)) / 8, 256>>>(p_embed, c_embed,
                                               ln_p_w, ln_p_b, ln_c_w, ln_c_b);

    // Decide inter_mask tail format
    const long inter_elems = (long)B_ * NP_ * NC_ * P_;
    const long mask_elems  = (long)B_ * NP_ * NC_;
    long extra = (long)out_size - inter_elems;
    void* mask_out = nullptr;
    int mask_mode = 0;
    if (extra >= mask_elems) {
        mask_out = (void*)(out + inter_elems); mask_mode = 1;      // float per entry
    } else if (extra == mask_elems / 4) {
        mask_out = (void*)(out + inter_elems); mask_mode = 2;      // byte per entry
    }

    // Persistent workers: 3 per SM
    int sms = 148;
    cudaDeviceGetAttribute(&sms, cudaDevAttrMultiProcessorCount, 0);
    int nworkers = sms * 3;
    if (nworkers > NTILES) nworkers = NTILES;

    gemm_mma_kernel<<<nworkers, 128, SM_TOTAL>>>(p_mask, c_mask, W_out, b_out, out,
                                                 mask_out, mask_mode);

    // Fallback for odd partial tails only
    if (mask_mode == 0 && extra > 0) {
        long n = extra < mask_elems ? extra : mask_elems;
        mask_float_kernel<<<(int)((n + 255) / 256), 256>>>(
            p_mask, c_mask, out + inter_elems, n);
    }
}

// round 17
// speedup vs baseline: 1.5351x; 1.0472x over previous
#include <cuda_runtime.h>
#include <cuda_bf16.h>
#include <cuda_fp16.h>
#include <cstdint>
#include <cstddef>

// Problem dims (fixed)
#define B_   2
#define NP_  512
#define NC_  512
#define D_   128
#define P_   128
#define NTILES 4096                       // B_*NP_*4 j-tiles

// ---------------- device scratch (allocation-free) ----------------
__device__ __align__(16) float    g_pn[(size_t)B_ * NP_ * D_];      // ln p, fp32
// c in mma-A-fragment layout: [blkm(64)][k16(8)][lane(32)][reg(4)] u32
__device__ __align__(16) uint32_t g_cfrag[(size_t)B_ * NC_ * D_ / 2];

__device__ __forceinline__ uint32_t smem_u32(const void* p) {
    uint32_t a;
    asm("{ .reg .u64 t; cvta.to.shared.u64 t, %1; cvt.u32.u64 %0, t; }"
        : "=r"(a) : "l"(p));
    return a;
}

// ---------------- SMEM layout ----------------
#define LDA      272                      // 128 fp16 = 256B + 16B pad
#define SM_P     0                        // 512 B
#define SM_BIAS  512                      // 512 B
#define SM_SCALE 1024                     // 2048 B
#define SM_B     3072
#define SM_TOTAL (SM_B + 128 * LDA)       // 37888 bytes

// ---------------------------------------------------------------------------
// LayerNorm: one warp per row. p rows -> fp32; c rows -> fragment-layout fp16.
// ---------------------------------------------------------------------------
__global__ void ln_kernel(const float* __restrict__ p_in,
                          const float* __restrict__ c_in,
                          const float* __restrict__ pw, const float* __restrict__ pb,
                          const float* __restrict__ cw, const float* __restrict__ cb) {
    int gwarp = (blockIdx.x * blockDim.x + threadIdx.x) >> 5;
    int lane  = threadIdx.x & 31;
    if (gwarp >= B_ * (NP_ + NC_)) return;

    bool is_p = gwarp < B_ * NP_;
    int row = is_p ? gwarp : gwarp - B_ * NP_;
    const float* src = is_p ? p_in : c_in;
    const float* w   = is_p ? pw : cw;
    const float* bb  = is_p ? pb : cb;

    float4 v = reinterpret_cast<const float4*>(src + (size_t)row * D_)[lane];

    float s = v.x + v.y + v.z + v.w;
    #pragma unroll
    for (int o = 16; o > 0; o >>= 1) s += __shfl_xor_sync(0xFFFFFFFFu, s, o);
    float mu = s * (1.0f / D_);

    float dx = v.x - mu, dy = v.y - mu, dz = v.z - mu, dw = v.w - mu;
    float q = dx * dx + dy * dy + dz * dz + dw * dw;
    #pragma unroll
    for (int o = 16; o > 0; o >>= 1) q += __shfl_xor_sync(0xFFFFFFFFu, q, o);
    float inv = rsqrtf(q * (1.0f / D_) + 1e-5f);

    float4 wv = reinterpret_cast<const float4*>(w)[lane];
    float4 bv = reinterpret_cast<const float4*>(bb)[lane];
    float o0 = dx * inv * wv.x + bv.x;
    float o1 = dy * inv * wv.y + bv.y;
    float o2 = dz * inv * wv.z + bv.z;
    float o3 = dw * inv * wv.w + bv.w;

    if (is_p) {
        float4 o4 = {o0, o1, o2, o3};
        reinterpret_cast<float4*>(g_pn + (size_t)row * D_)[lane] = o4;
    } else {
        // scatter into mma A-fragment layout
        __half2 h01 = __floats2half2_rn(o0, o1);
        __half2 h23 = __floats2half2_rn(o2, o3);
        uint32_t wrd[2];
        wrd[0] = *reinterpret_cast<uint32_t*>(&h01);   // k = 4*lane, 4*lane+1
        wrd[1] = *reinterpret_cast<uint32_t*>(&h23);   // k = 4*lane+2, +3
        const int r = row & 15;
        const size_t blkm = (size_t)(row >> 4);
        const int k0 = lane * 4;
        #pragma unroll
        for (int m = 0; m < 2; m++) {
            int kg  = k0 + 2 * m;
            int k16 = kg >> 4;
            int kk  = kg & 15;
            int lp  = (r & 7) * 4 + ((kk >> 1) & 3);
            int rg  = (r >> 3) + 2 * (kk >> 3);
            g_cfrag[((blkm * 8 + k16) * 32 + lp) * 4 + rg] = wrd[m];
        }
    }
}

// ---------------------------------------------------------------------------
// PERSISTENT-WORKER fp16 warp-MMA interaction kernel, A direct from GMEM,
// h-PERMUTED B so the epilogue needs no shuffles (each thread natively owns
// 4 contiguous output columns). Grid = nworkers (~3 x SMs). 128 threads =
// 4 warps in 2(m) x 2(n), warp tile 64x64.
// mask_mode: 0=none, 1=float per entry, 2=byte per entry.
// ---------------------------------------------------------------------------
__global__ __launch_bounds__(128, 3)
void gemm_mma_kernel(const int* __restrict__ p_mask,
                     const int* __restrict__ c_mask,
                     const float* __restrict__ W,
                     const float* __restrict__ bias,
                     float* __restrict__ out,
                     void* __restrict__ mask_out, int mask_mode) {
    extern __shared__ char smem[];
    const uint32_t sb = smem_u32(smem);
    float* p_s     = reinterpret_cast<float*>(smem + SM_P);
    float* bias_s  = reinterpret_cast<float*>(smem + SM_BIAS);
    float* scale_s = reinterpret_cast<float*>(smem + SM_SCALE);

    const int t = threadIdx.x;
    const int wid  = t >> 5;
    const int lane = t & 31;
    const int nw = gridDim.x;
    const int w  = blockIdx.x;

    const int start = (int)(((long)w * NTILES) / nw);
    const int end   = (int)(((long)(w + 1) * NTILES) / nw);
    if (start >= end) return;

    // --- bias load (once) ---
    if (t < 32) {
        reinterpret_cast<float4*>(bias_s)[t] =
            reinterpret_cast<const float4*>(bias)[t];
    }

    const int wm = wid & 1;      // m: 64 j-rows each
    const int wn = wid >> 1;     // n: 64 h-cols each
    const uint32_t b_lane = (uint32_t)((wn * 64 + (lane & 15)) * LDA + (lane >> 4) * 16);
    const uint32_t bhbase = sb + SM_B + b_lane;

    const int g   = lane >> 2;
    const int tig = lane & 3;

    int prev_bi = -1;

    #pragma unroll 1
    for (int tidx = start; tidx < end; tidx++) {
        const int b  = tidx >> 11;
        const int bi = tidx >> 2;            // (b*512 + i)
        const int jt = tidx & 3;
        const int j0 = jt * 128;

        // --- rebuild per-i state on i change ---
        if (bi != prev_bi) {
            __syncthreads();     // all warps done with previous B/scale
            if (t < 32) {
                float4 v = reinterpret_cast<const float4*>(
                    g_pn + ((size_t)bi) * D_)[t];
                p_s[t * 4 + 0] = v.x; p_s[t * 4 + 1] = v.y;
                p_s[t * 4 + 2] = v.z; p_s[t * 4 + 3] = v.w;
            }
            {
                const bool pm = p_mask[bi] != 0;
                const int4 cm = reinterpret_cast<const int4*>(c_mask + b * NC_)[t];
                float4 sc;
                sc.x = (pm && cm.x) ? 1.0f : 0.0f;
                sc.y = (pm && cm.y) ? 1.0f : 0.0f;
                sc.z = (pm && cm.z) ? 1.0f : 0.0f;
                sc.w = (pm && cm.w) ? 1.0f : 0.0f;
                reinterpret_cast<float4*>(scale_s)[t] = sc;
            }
            __syncthreads();     // p_s + scale_s visible

            // fused inter_mask row write (only owner of jt==0 writes)
            if (jt == 0) {
                if (mask_mode == 1) {
                    float* mrow = reinterpret_cast<float*>(mask_out) + (size_t)bi * NC_;
                    reinterpret_cast<float4*>(mrow)[t] =
                        reinterpret_cast<float4*>(scale_s)[t];
                } else if (mask_mode == 2) {
                    unsigned char* mrow = reinterpret_cast<unsigned char*>(mask_out)
                                        + (size_t)bi * NC_;
                    float4 sc = reinterpret_cast<float4*>(scale_s)[t];
                    uchar4 u;
                    u.x = (unsigned char)(sc.x != 0.0f);
                    u.y = (unsigned char)(sc.y != 0.0f);
                    u.z = (unsigned char)(sc.z != 0.0f);
                    u.w = (unsigned char)(sc.w != 0.0f);
                    reinterpret_cast<uchar4*>(mrow)[t] = u;
                }
            }

            // build B = W o p_i, fp16, with h-PERMUTED rows:
            // smem row r holds W row perm(r); perm interleaves so each thread's
            // fragment-pair cols are 4 contiguous true-h values.
            #pragma unroll 4
            for (int u = t; u < 4096; u += 128) {
                int row = u >> 5;          // smem row
                int q   = u & 31;          // float4 index
                int pr  = (row & ~15) | ((((row & 7) >> 1)) << 2)
                        | (((row >> 3) & 1) << 1) | (row & 1);
                float4 w4 = reinterpret_cast<const float4*>(W + (size_t)pr * D_)[q];
                int k = q * 4;
                __half2 h01 = __floats2half2_rn(w4.x * p_s[k + 0], w4.y * p_s[k + 1]);
                __half2 h23 = __floats2half2_rn(w4.z * p_s[k + 2], w4.w * p_s[k + 3]);
                uint2 hw;
                hw.x = *reinterpret_cast<uint32_t*>(&h01);
                hw.y = *reinterpret_cast<uint32_t*>(&h23);
                *reinterpret_cast<uint2*>(smem + SM_B + row * LDA + k * 2) = hw;
            }
            __syncthreads();     // B visible to all warps
            prev_bi = bi;
        }

        // --- A fragment base for this tile (L2-hot, coalesced uint4 loads) ---
        const int bjrow = b * NC_ + j0 + wm * 64; // global c row base (mult of 16)
        const uint4* abase4 = reinterpret_cast<const uint4*>(g_cfrag)
                            + ((size_t)(bjrow >> 4)) * 256 + lane;

        // --- Mainloop: warp tile 64x64, A via LDG, B via LDSM ---
        float acc[4][8][4];
        #pragma unroll
        for (int mf = 0; mf < 4; mf++)
            #pragma unroll
            for (int nf = 0; nf < 8; nf++)
                #pragma unroll
                for (int r = 0; r < 4; r++) acc[mf][nf][r] = 0.0f;

        #pragma unroll
        for (int ks = 0; ks < 8; ks++) {
            uint32_t bh[4][4];
            #pragma unroll
            for (int np = 0; np < 4; np++) {
                uint32_t addr = bhbase + np * (16 * LDA) + ks * 32;
                asm volatile("ldmatrix.sync.aligned.m8n8.x4.shared.b16 {%0,%1,%2,%3}, [%4];"
                             : "=r"(bh[np][0]), "=r"(bh[np][1]),
                               "=r"(bh[np][2]), "=r"(bh[np][3]) : "r"(addr));
            }
            #pragma unroll
            for (int mf = 0; mf < 4; mf++) {
                const uint4 av = __ldg(abase4 + mf * 256 + ks * 32);
                #pragma unroll
                for (int np = 0; np < 4; np++) {
                    #pragma unroll
                    for (int sel = 0; sel < 2; sel++) {
                        const int nf = np * 2 + sel;
                        asm volatile(
                            "mma.sync.aligned.m16n8k16.row.col.f32.f16.f16.f32 "
                            "{%0,%1,%2,%3}, {%4,%5,%6,%7}, {%8,%9}, {%0,%1,%2,%3};"
                            : "+f"(acc[mf][nf][0]), "+f"(acc[mf][nf][1]),
                              "+f"(acc[mf][nf][2]), "+f"(acc[mf][nf][3])
                            : "r"(av.x), "r"(av.y), "r"(av.z), "r"(av.w),
                              "r"(bh[np][sel]), "r"(bh[np][2 + sel]));
                    }
                }
            }
        }

        // --- Epilogue: shuffle-free. Thread owns 4 contiguous true-h cols
        //     per fragment pair: h = wn*64 + 16*p4 + 4*tig + {0,1,2,3}. ---
        #pragma unroll
        for (int mf = 0; mf < 4; mf++) {
            const int jl = j0 + wm * 64 + mf * 16 + g;
            const float s0 = scale_s[jl];
            const float s1 = scale_s[jl + 8];
            float* rowp  = out + ((size_t)bi * NC_ + jl) * P_ + wn * 64;
            float* row1p = rowp + (size_t)8 * P_;
            #pragma unroll
            for (int p4 = 0; p4 < 4; p4++) {
                const int nf0 = p4 * 2, nf1 = nf0 + 1;
                const int col = p4 * 16 + tig * 4;
                const float4 bb = *reinterpret_cast<const float4*>(
                    bias_s + wn * 64 + col);
                float4 v0, v1;
                v0.x = (acc[mf][nf0][0] + bb.x) * s0;
                v0.y = (acc[mf][nf0][1] + bb.y) * s0;
                v0.z = (acc[mf][nf1][0] + bb.z) * s0;
                v0.w = (acc[mf][nf1][1] + bb.w) * s0;
                v1.x = (acc[mf][nf0][2] + bb.x) * s1;
                v1.y = (acc[mf][nf0][3] + bb.y) * s1;
                v1.z = (acc[mf][nf1][2] + bb.z) * s1;
                v1.w = (acc[mf][nf1][3] + bb.w) * s1;
                asm volatile("st.global.cs.v4.f32 [%0], {%1, %2, %3, %4};"
                             :: "l"(rowp + col), "f"(v0.x), "f"(v0.y), "f"(v0.z), "f"(v0.w)
                             : "memory");
                asm volatile("st.global.cs.v4.f32 [%0], {%1, %2, %3, %4};"
                             :: "l"(row1p + col), "f"(v1.x), "f"(v1.y), "f"(v1.z), "f"(v1.w)
                             : "memory");
            }
        }
    }
}

// ---------------------------------------------------------------------------
// Fallback inter_mask kernel (only for unexpected tail sizes)
// ---------------------------------------------------------------------------
__global__ void mask_float_kernel(const int* __restrict__ p_mask,
                                  const int* __restrict__ c_mask,
                                  float* __restrict__ out, long n) {
    long idx = (long)blockIdx.x * blockDim.x + threadIdx.x;
    if (idx >= n) return;
    int j  = (int)(idx & (NC_ - 1));
    long bi = idx >> 9;
    int i  = (int)(bi & (NP_ - 1));
    int b  = (int)(bi >> 9);
    out[idx] = (p_mask[b * NP_ + i] && c_mask[b * NC_ + j]) ? 1.0f : 0.0f;
}

// ---------------------------------------------------------------------------
extern "C" void kernel_launch(void* const* d_in, const int* in_sizes, int n_in,
                              void* d_out, int out_size) {
    const float* p_embed = (const float*)d_in[0];
    const float* c_embed = (const float*)d_in[1];
    const int*   p_mask  = (const int*)d_in[2];
    const int*   c_mask  = (const int*)d_in[3];
    const float* ln_p_w  = (const float*)d_in[4];
    const float* ln_p_b  = (const float*)d_in[5];
    const float* ln_c_w  = (const float*)d_in[6];
    const float* ln_c_b  = (const float*)d_in[7];
    const float* W_out   = (const float*)d_in[8];
    const float* b_out   = (const float*)d_in[9];
    float* out = (float*)d_out;

    cudaFuncSetAttribute(gemm_mma_kernel,
                         cudaFuncAttributeMaxDynamicSharedMemorySize, SM_TOTAL);

    // LayerNorm (p -> fp32, c -> fragment-layout fp16)
    ln_kernel<<<(B_ * (NP_ + NC_)) / 8, 256>>>(p_embed, c_embed,
                                               ln_p_w, ln_p_b, ln_c_w, ln_c_b);

    // Decide inter_mask tail format
    const long inter_elems = (long)B_ * NP_ * NC_ * P_;
    const long mask_elems  = (long)B_ * NP_ * NC_;
    long extra = (long)out_size - inter_elems;
    void* mask_out = nullptr;
    int mask_mode = 0;
    if (extra >= mask_elems) {
        mask_out = (void*)(out + inter_elems); mask_mode = 1;      // float per entry
    } else if (extra == mask_elems / 4) {
        mask_out = (void*)(out + inter_elems); mask_mode = 2;      // byte per entry
    }

    // Persistent workers: 3 per SM
    int sms = 148;
    cudaDeviceGetAttribute(&sms, cudaDevAttrMultiProcessorCount, 0);
    int nworkers = sms * 3;
    if (nworkers > NTILES) nworkers = NTILES;

    gemm_mma_kernel<<<nworkers, 128, SM_TOTAL>>>(p_mask, c_mask, W_out, b_out, out,
                                                 mask_out, mask_mode);

    // Fallback for odd partial tails only
    if (mask_mode == 0 && extra > 0) {
        long n = extra < mask_elems ? extra : mask_elems;
        mask_float_kernel<<<(int)((n + 255) / 256), 256>>>(
            p_mask, c_mask, out + inter_elems, n);
    }
}